// round 6
// baseline (speedup 1.0000x reference)
#include <cuda_runtime.h>
#include <cuda_bf16.h>

#define BB 128   // batch
#define NN 50    // entities per doc
#define KK 20    // neighbors
#define DD 128   // embedding dim
#define NK (NN*KK)          // 1000
#define BN (BB*NN)          // 6400
#define TOT (BB*NN*KK)      // 128000

// scratch
__device__ float g_exp[TOT];          // transposed: exp(logit)[nk][b]
__device__ float g_den[1024];         // softmax denominators per (n,k)
__device__ float g_rel_dot[128];      // R=100, padded
__device__ float g_agg[BN * 2 * DD];  // [bn][256] = [ee | weighted-neighbor-sum]

typedef unsigned long long ull;

// ---- packed f32x2 helpers (sm_103a) --------------------------------------
__device__ __forceinline__ ull pack2(float lo, float hi) {
    ull r;
    asm("mov.b64 %0, {%1, %2};" : "=l"(r) : "f"(lo), "f"(hi));
    return r;
}
__device__ __forceinline__ void unpack2(ull v, float& lo, float& hi) {
    asm("mov.b64 {%0, %1}, %2;" : "=f"(lo), "=f"(hi) : "l"(v));
}
__device__ __forceinline__ ull fma2(ull a, ull b, ull c) {
    ull d;
    asm("fma.rn.f32x2 %0, %1, %2, %3;" : "=l"(d) : "l"(a), "l"(b), "l"(c));
    return d;
}

// ---------------------------------------------------------------------------
// K0: zero g_den; rel_dot[r] = dot(rel_emb[r], w2)  (100 warps, 25 blocks)
// ---------------------------------------------------------------------------
__global__ __launch_bounds__(128) void k_pre(
    const float* __restrict__ rel_emb,
    const float* __restrict__ W_att)
{
    int gtid = blockIdx.x * 128 + threadIdx.x;
    if (gtid < 1024) g_den[gtid] = 0.0f;

    int warp = gtid >> 5;
    int lane = threadIdx.x & 31;
    if (warp >= 100) return;

    float4 a  = ((const float4*)(rel_emb + (size_t)warp * DD))[lane];
    float4 wv = ((const float4*)(W_att + 2 * DD))[lane];
    float s = a.x*wv.x + a.y*wv.y + a.z*wv.z + a.w*wv.w;
    #pragma unroll
    for (int off = 16; off > 0; off >>= 1)
        s += __shfl_xor_sync(0xffffffffu, s, off);
    if (lane == 0) g_rel_dot[warp] = s;
}

// ---------------------------------------------------------------------------
// K1: logits -> exp + denominator atomics.
// One block per (b,n), 5 warps; warp w handles k = 4w..4w+3 AND redundantly
// computes ee_dot (ee row L1-hot across the block). MLP=7 float4 loads.
// ---------------------------------------------------------------------------
__global__ __launch_bounds__(160) void k_logits(
    const int* __restrict__ entity_ids,
    const int* __restrict__ adj_entity,
    const int* __restrict__ adj_relation,
    const float* __restrict__ ent_emb,
    const float* __restrict__ W_att,
    const float* __restrict__ b_att)
{
    int bn   = blockIdx.x;
    int warp = threadIdx.x >> 5;     // 0..4
    int lane = threadIdx.x & 31;
    int b    = bn / NN;
    int n    = bn - b * NN;
    int k0   = warp * 4;

    int eid = entity_ids[bn];
    // (eid*20+k0)*4B = 80*eid + 16*warp  -> 16B aligned
    int4 nid = *(const int4*)(adj_entity   + eid * KK + k0);
    int4 rid = *(const int4*)(adj_relation + eid * KK + k0);

    const float4* w0p = (const float4*)(W_att);
    const float4* w1p = (const float4*)(W_att + DD);
    float4 w0 = w0p[lane];
    float4 w1 = w1p[lane];

    float4 ee = ((const float4*)(ent_emb + (size_t)eid   * DD))[lane];
    float4 v0 = ((const float4*)(ent_emb + (size_t)nid.x * DD))[lane];
    float4 v1 = ((const float4*)(ent_emb + (size_t)nid.y * DD))[lane];
    float4 v2 = ((const float4*)(ent_emb + (size_t)nid.z * DD))[lane];
    float4 v3 = ((const float4*)(ent_emb + (size_t)nid.w * DD))[lane];

    float se = ee.x*w0.x + ee.y*w0.y + ee.z*w0.z + ee.w*w0.w;
    float s0 = v0.x*w1.x + v0.y*w1.y + v0.z*w1.z + v0.w*w1.w;
    float s1 = v1.x*w1.x + v1.y*w1.y + v1.z*w1.z + v1.w*w1.w;
    float s2 = v2.x*w1.x + v2.y*w1.y + v2.z*w1.z + v2.w*w1.w;
    float s3 = v3.x*w1.x + v3.y*w1.y + v3.z*w1.z + v3.w*w1.w;

    #pragma unroll
    for (int off = 16; off > 0; off >>= 1) {
        se += __shfl_xor_sync(0xffffffffu, se, off);
        s0 += __shfl_xor_sync(0xffffffffu, s0, off);
        s1 += __shfl_xor_sync(0xffffffffu, s1, off);
        s2 += __shfl_xor_sync(0xffffffffu, s2, off);
        s3 += __shfl_xor_sync(0xffffffffu, s3, off);
    }

    if (lane == 0) {
        float base = se + b_att[0];
        float e0 = __expf(fmaxf(s0 + base + g_rel_dot[rid.x], 0.0f));
        float e1 = __expf(fmaxf(s1 + base + g_rel_dot[rid.y], 0.0f));
        float e2 = __expf(fmaxf(s2 + base + g_rel_dot[rid.z], 0.0f));
        float e3 = __expf(fmaxf(s3 + base + g_rel_dot[rid.w], 0.0f));
        int nk = n * KK + k0;
        float* dst = g_exp + nk * BB + b;
        dst[0 * BB] = e0;
        dst[1 * BB] = e1;
        dst[2 * BB] = e2;
        dst[3 * BB] = e3;
        atomicAdd(&g_den[nk + 0], e0);
        atomicAdd(&g_den[nk + 1], e1);
        atomicAdd(&g_den[nk + 2], e2);
        atomicAdd(&g_den[nk + 3], e3);
    }
}

// ---------------------------------------------------------------------------
// K2: gather. 64-thread block per (b,n); thread = dim pair (2d, 2d+1).
// 20 independent LDG.64 -> 160 B in flight per thread; packed fma.rn.f32x2
// with pre-packed attention weights (att = exp/den) from shared.
// ---------------------------------------------------------------------------
__global__ __launch_bounds__(64) void k_gather(
    const int* __restrict__ entity_ids,
    const int* __restrict__ adj_entity,
    const float* __restrict__ ent_emb)
{
    __shared__ int s_nid[KK];
    __shared__ ull s_att2[KK];

    int bn = blockIdx.x;
    int b  = bn / NN;
    int n  = bn - b * NN;
    int t  = threadIdx.x;

    int eid = entity_ids[bn];
    if (t < KK) {
        s_nid[t] = adj_entity[eid * KK + t];
        int nk = n * KK + t;
        float a = __fdividef(g_exp[nk * BB + b], g_den[nk]);
        s_att2[t] = pack2(a, a);
    }
    __syncthreads();

    int d0 = 2 * t;
    ull ee2 = *(const ull*)(ent_emb + (size_t)eid * DD + d0);

    ull v[KK];
    #pragma unroll
    for (int k = 0; k < KK; k++)
        v[k] = *(const ull*)(ent_emb + (size_t)s_nid[k] * DD + d0);

    ull acc = 0ull;   // (+0.0f, +0.0f)
    #pragma unroll
    for (int k = 0; k < KK; k++)
        acc = fma2(s_att2[k], v[k], acc);

    *(ull*)(g_agg + (size_t)bn * 2 * DD + d0)      = ee2;
    *(ull*)(g_agg + (size_t)bn * 2 * DD + DD + d0) = acc;
}

// ---------------------------------------------------------------------------
// K3: out[6400,128] = relu(agg[6400,256] @ W_conv + b_conv)
// 32 rows/block, 256 threads; thread = 2 outputs x 8 rows; packed f32x2.
// All 200 blocks resident; W_conv L2 traffic = 25 MB.
// ---------------------------------------------------------------------------
#define GROWS  32
#define GPITCH 36     // floats per j-row: 144 B (16B-aligned: 144 = 9*16)

__global__ __launch_bounds__(256) void k_gemm(
    const float* __restrict__ W_conv,
    const float* __restrict__ b_conv,
    float* __restrict__ out)
{
    __shared__ float sT[2 * DD * GPITCH];   // [256][36] = 36 KB

    int t   = threadIdx.x;
    int bn0 = blockIdx.x * GROWS;

    // stage 32x256 tile transposed: sT[j][row]
    {
        int row = t & 31;          // 0..31
        int jc  = t >> 5;          // 0..7 -> chunk of 32 j
        const float4* src = (const float4*)(g_agg + (size_t)(bn0 + row) * 2 * DD + jc * 32);
        #pragma unroll
        for (int c = 0; c < 8; c++) {
            float4 v = src[c];
            int j = jc * 32 + c * 4;
            sT[(j + 0) * GPITCH + row] = v.x;
            sT[(j + 1) * GPITCH + row] = v.y;
            sT[(j + 2) * GPITCH + row] = v.z;
            sT[(j + 3) * GPITCH + row] = v.w;
        }
    }
    __syncthreads();

    int p  = t & 63;          // output pair index -> d0 = 2p
    int d0 = 2 * p;
    int rg = t >> 6;          // 0..3 -> rows rg*8 .. rg*8+7

    ull acc[2][4];
    {
        ull i0 = pack2(b_conv[d0],     b_conv[d0]);
        ull i1 = pack2(b_conv[d0 + 1], b_conv[d0 + 1]);
        #pragma unroll
        for (int rp = 0; rp < 4; rp++) { acc[0][rp] = i0; acc[1][rp] = i1; }
    }

    const float* sb = sT + rg * 8;
    #pragma unroll 4
    for (int j = 0; j < 2 * DD; j++) {
        float2 w = *(const float2*)(W_conv + j * DD + d0);
        ull w0 = pack2(w.x, w.x);
        ull w1 = pack2(w.y, w.y);
        ulonglong2 pa = *(const ulonglong2*)(sb + j * GPITCH);       // rows 0-3
        ulonglong2 pb = *(const ulonglong2*)(sb + j * GPITCH + 4);   // rows 4-7
        acc[0][0] = fma2(pa.x, w0, acc[0][0]);
        acc[1][0] = fma2(pa.x, w1, acc[1][0]);
        acc[0][1] = fma2(pa.y, w0, acc[0][1]);
        acc[1][1] = fma2(pa.y, w1, acc[1][1]);
        acc[0][2] = fma2(pb.x, w0, acc[0][2]);
        acc[1][2] = fma2(pb.x, w1, acc[1][2]);
        acc[0][3] = fma2(pb.y, w0, acc[0][3]);
        acc[1][3] = fma2(pb.y, w1, acc[1][3]);
    }

    #pragma unroll
    for (int rp = 0; rp < 4; rp++) {
        float lo0, hi0, lo1, hi1;
        unpack2(acc[0][rp], lo0, hi0);   // rows r0, r0+1 @ d0
        unpack2(acc[1][rp], lo1, hi1);   // rows r0, r0+1 @ d0+1
        int r0 = bn0 + rg * 8 + rp * 2;
        float2 o0 = make_float2(fmaxf(lo0, 0.0f), fmaxf(lo1, 0.0f));
        float2 o1 = make_float2(fmaxf(hi0, 0.0f), fmaxf(hi1, 0.0f));
        *(float2*)(out + (size_t)r0 * DD + d0)       = o0;
        *(float2*)(out + (size_t)(r0 + 1) * DD + d0) = o1;
    }
}

// ---------------------------------------------------------------------------
extern "C" void kernel_launch(void* const* d_in, const int* in_sizes, int n_in,
                              void* d_out, int out_size)
{
    const int*   entity_ids = (const int*)  d_in[0];
    const int*   adj_entity = (const int*)  d_in[1];
    const int*   adj_rel    = (const int*)  d_in[2];
    const float* ent_emb    = (const float*)d_in[3];
    const float* rel_emb    = (const float*)d_in[4];
    const float* W_att      = (const float*)d_in[5];
    const float* b_att      = (const float*)d_in[6];
    const float* W_conv     = (const float*)d_in[7];
    const float* b_conv     = (const float*)d_in[8];
    float* out = (float*)d_out;

    k_pre<<<25, 128>>>(rel_emb, W_att);

    k_logits<<<BN, 160>>>(entity_ids, adj_entity, adj_rel,
                          ent_emb, W_att, b_att);

    k_gather<<<BN, 64>>>(entity_ids, adj_entity, ent_emb);

    k_gemm<<<BN / GROWS, 256>>>(W_conv, b_conv, out);
}

// round 7
// speedup vs baseline: 1.2599x; 1.2599x over previous
#include <cuda_runtime.h>
#include <cuda_bf16.h>

#define BB 128   // batch
#define NN 50    // entities per doc
#define KK 20    // neighbors
#define DD 128   // embedding dim
#define NK (NN*KK)          // 1000
#define BN (BB*NN)          // 6400
#define TOT (BB*NN*KK)      // 128000

// scratch
__device__ float g_exp[TOT];          // transposed: exp(logit)[nk][b]
__device__ float g_den[1024];         // softmax denominators per (n,k)
__device__ float g_ee_dot[BN];
__device__ float g_rel_dot[128];      // R=100, padded
__device__ float g_agg[BN * 2 * DD];  // [bn][256] = [ee | weighted-nb-sum]

typedef unsigned long long ull;

// ---- packed f32x2 helpers (sm_103a) --------------------------------------
__device__ __forceinline__ ull pack2(float lo, float hi) {
    ull r;
    asm("mov.b64 %0, {%1, %2};" : "=l"(r) : "f"(lo), "f"(hi));
    return r;
}
__device__ __forceinline__ void unpack2(ull v, float& lo, float& hi) {
    asm("mov.b64 {%0, %1}, %2;" : "=f"(lo), "=f"(hi) : "l"(v));
}
__device__ __forceinline__ ull fma2(ull a, ull b, ull c) {
    ull d;
    asm("fma.rn.f32x2 %0, %1, %2, %3;" : "=l"(d) : "l"(a), "l"(b), "l"(c));
    return d;
}

// ---------------------------------------------------------------------------
// K0: zero g_den; ee_dot[bn] = dot(ee, w0) (6400 warps);
//     rel_dot[r] = dot(rel_emb[r], w2) (100 warps). 813 blocks x 256.
// ---------------------------------------------------------------------------
__global__ __launch_bounds__(256) void k_pre(
    const int* __restrict__ entity_ids,
    const float* __restrict__ ent_emb,
    const float* __restrict__ rel_emb,
    const float* __restrict__ W_att)
{
    int gtid = blockIdx.x * 256 + threadIdx.x;
    if (gtid < 1024) g_den[gtid] = 0.0f;

    int warp = gtid >> 5;
    int lane = threadIdx.x & 31;
    if (warp >= BN + 100) return;

    const float4* row;
    const float4* w;
    if (warp < BN) {
        int eid = entity_ids[warp];
        row = (const float4*)(ent_emb + (size_t)eid * DD);
        w   = (const float4*)(W_att);            // w0
    } else {
        row = (const float4*)(rel_emb + (size_t)(warp - BN) * DD);
        w   = (const float4*)(W_att + 2 * DD);   // w2
    }
    float4 a = row[lane], wv = w[lane];
    float s = a.x*wv.x + a.y*wv.y + a.z*wv.z + a.w*wv.w;
    #pragma unroll
    for (int off = 16; off > 0; off >>= 1)
        s += __shfl_xor_sync(0xffffffffu, s, off);
    if (lane == 0) {
        if (warp < BN) g_ee_dot[warp] = s;
        else           g_rel_dot[warp - BN] = s;
    }
}

// ---------------------------------------------------------------------------
// K1: one warp per (bn, k-quad): 4 neighbor rows in flight (MLP=4+w),
// 4 interleaved butterflies; lanes 0-3 each finish one k (exp + atomic den).
// ---------------------------------------------------------------------------
__global__ __launch_bounds__(256) void k_logits(
    const int* __restrict__ entity_ids,
    const int* __restrict__ adj_entity,
    const int* __restrict__ adj_relation,
    const float* __restrict__ ent_emb,
    const float* __restrict__ W_att,
    const float* __restrict__ b_att)
{
    int warp = (blockIdx.x * blockDim.x + threadIdx.x) >> 5;  // 0..TOT/4-1
    int lane = threadIdx.x & 31;

    int bn = warp / 5;
    int k0 = (warp - bn * 5) * 4;     // 0,4,8,12,16
    int b  = bn / NN;
    int n  = bn - b * NN;

    int eid = entity_ids[bn];
    int4 nid = *(const int4*)(adj_entity   + eid * KK + k0);  // 16B-aligned
    int4 rid = *(const int4*)(adj_relation + eid * KK + k0);

    float4 wv = ((const float4*)(W_att + DD))[lane];

    float4 v0 = ((const float4*)(ent_emb + (size_t)nid.x * DD))[lane];
    float4 v1 = ((const float4*)(ent_emb + (size_t)nid.y * DD))[lane];
    float4 v2 = ((const float4*)(ent_emb + (size_t)nid.z * DD))[lane];
    float4 v3 = ((const float4*)(ent_emb + (size_t)nid.w * DD))[lane];

    float s0 = v0.x*wv.x + v0.y*wv.y + v0.z*wv.z + v0.w*wv.w;
    float s1 = v1.x*wv.x + v1.y*wv.y + v1.z*wv.z + v1.w*wv.w;
    float s2 = v2.x*wv.x + v2.y*wv.y + v2.z*wv.z + v2.w*wv.w;
    float s3 = v3.x*wv.x + v3.y*wv.y + v3.z*wv.z + v3.w*wv.w;

    #pragma unroll
    for (int off = 16; off > 0; off >>= 1) {
        s0 += __shfl_xor_sync(0xffffffffu, s0, off);
        s1 += __shfl_xor_sync(0xffffffffu, s1, off);
        s2 += __shfl_xor_sync(0xffffffffu, s2, off);
        s3 += __shfl_xor_sync(0xffffffffu, s3, off);
    }

    if (lane < 4) {
        float s  = (lane == 0) ? s0 : (lane == 1) ? s1 : (lane == 2) ? s2 : s3;
        int   rv = (lane == 0) ? rid.x : (lane == 1) ? rid.y
                 : (lane == 2) ? rid.z : rid.w;
        float base = g_ee_dot[bn] + b_att[0];
        float e = __expf(fmaxf(s + base + g_rel_dot[rv], 0.0f));
        int nk = n * KK + k0 + lane;
        g_exp[nk * BB + b] = e;
        atomicAdd(&g_den[nk], e);
    }
}

// ---------------------------------------------------------------------------
// K2: gather. 64-thread block per (b,n); thread = dim pair (2d, 2d+1).
// 20 independent LDG.64 in flight; packed fma.rn.f32x2.
// ---------------------------------------------------------------------------
__global__ __launch_bounds__(64) void k_gather(
    const int* __restrict__ entity_ids,
    const int* __restrict__ adj_entity,
    const float* __restrict__ ent_emb)
{
    __shared__ int s_nid[KK];
    __shared__ ull s_att2[KK];

    int bn = blockIdx.x;
    int b  = bn / NN;
    int n  = bn - b * NN;
    int t  = threadIdx.x;

    int eid = entity_ids[bn];
    if (t < KK) {
        s_nid[t] = adj_entity[eid * KK + t];
        int nk = n * KK + t;
        float a = __fdividef(g_exp[nk * BB + b], g_den[nk]);
        s_att2[t] = pack2(a, a);
    }
    __syncthreads();

    int d0 = 2 * t;
    ull ee2 = *(const ull*)(ent_emb + (size_t)eid * DD + d0);

    ull v[KK];
    #pragma unroll
    for (int k = 0; k < KK; k++)
        v[k] = *(const ull*)(ent_emb + (size_t)s_nid[k] * DD + d0);

    ull acc = 0ull;
    #pragma unroll
    for (int k = 0; k < KK; k++)
        acc = fma2(s_att2[k], v[k], acc);

    *(ull*)(g_agg + (size_t)bn * 2 * DD + d0)      = ee2;
    *(ull*)(g_agg + (size_t)bn * 2 * DD + DD + d0) = acc;
}

// ---------------------------------------------------------------------------
// K3: out[6400,128] = relu(agg[6400,256] @ W_conv + b_conv)
// 16 rows/block, 128 threads, grid=400; thread = 2 outputs x 8 rows.
// W_conv fetched through an explicit 8-deep register double-buffer so the
// LDG latency is decoupled from the FFMA2 stream (prev version exposed it).
// ---------------------------------------------------------------------------
#define GROWS  16
#define GPITCH 20     // floats per j-row: 80B (16B-aligned)

__global__ __launch_bounds__(128) void k_gemm(
    const float* __restrict__ W_conv,
    const float* __restrict__ b_conv,
    float* __restrict__ out)
{
    __shared__ float sT[2 * DD * GPITCH];   // [256][20] = 20 KB

    int t   = threadIdx.x;
    int bn0 = blockIdx.x * GROWS;

    // stage 16x256 tile transposed: sT[j][row]
    {
        int row = t & 15;
        int jc  = t >> 4;
        const float4* src = (const float4*)(g_agg + (size_t)(bn0 + row) * 2 * DD + jc * 32);
        #pragma unroll
        for (int c = 0; c < 8; c++) {
            float4 v = src[c];
            int j = jc * 32 + c * 4;
            sT[(j + 0) * GPITCH + row] = v.x;
            sT[(j + 1) * GPITCH + row] = v.y;
            sT[(j + 2) * GPITCH + row] = v.z;
            sT[(j + 3) * GPITCH + row] = v.w;
        }
    }
    __syncthreads();

    int p  = t & 63;
    int d0 = 2 * p;
    int rg = t >> 6;          // 0/1 -> rows rg*8 .. rg*8+7

    ull acc[2][4];
    {
        ull i0 = pack2(b_conv[d0],     b_conv[d0]);
        ull i1 = pack2(b_conv[d0 + 1], b_conv[d0 + 1]);
        #pragma unroll
        for (int rp = 0; rp < 4; rp++) { acc[0][rp] = i0; acc[1][rp] = i1; }
    }

    const float* Wp = W_conv + d0;
    const float* sb = sT + rg * 8;

    // prologue: fill prefetch buffer with j = 0..7
    float2 wb[8];
    #pragma unroll
    for (int i = 0; i < 8; i++)
        wb[i] = *(const float2*)(Wp + i * DD);

    #pragma unroll 1
    for (int jt = 0; jt < 2 * DD; jt += 8) {
        float2 wc[8];
        #pragma unroll
        for (int i = 0; i < 8; i++) wc[i] = wb[i];

        // branchless wrap-around prefetch of next chunk (8 LDG.64 in flight)
        int jn = (jt + 8) & (2 * DD - 1);
        #pragma unroll
        for (int i = 0; i < 8; i++)
            wb[i] = *(const float2*)(Wp + (jn + i) * DD);

        #pragma unroll
        for (int i = 0; i < 8; i++) {
            int j = jt + i;
            ull w0 = pack2(wc[i].x, wc[i].x);
            ull w1 = pack2(wc[i].y, wc[i].y);
            ulonglong2 pa = *(const ulonglong2*)(sb + j * GPITCH);       // rows 0-3
            ulonglong2 pb = *(const ulonglong2*)(sb + j * GPITCH + 4);   // rows 4-7
            acc[0][0] = fma2(pa.x, w0, acc[0][0]);
            acc[1][0] = fma2(pa.x, w1, acc[1][0]);
            acc[0][1] = fma2(pa.y, w0, acc[0][1]);
            acc[1][1] = fma2(pa.y, w1, acc[1][1]);
            acc[0][2] = fma2(pb.x, w0, acc[0][2]);
            acc[1][2] = fma2(pb.x, w1, acc[1][2]);
            acc[0][3] = fma2(pb.y, w0, acc[0][3]);
            acc[1][3] = fma2(pb.y, w1, acc[1][3]);
        }
    }

    #pragma unroll
    for (int rp = 0; rp < 4; rp++) {
        float lo0, hi0, lo1, hi1;
        unpack2(acc[0][rp], lo0, hi0);   // rows r0, r0+1 @ d0
        unpack2(acc[1][rp], lo1, hi1);   // rows r0, r0+1 @ d0+1
        int r0 = bn0 + rg * 8 + rp * 2;
        float2 o0 = make_float2(fmaxf(lo0, 0.0f), fmaxf(lo1, 0.0f));
        float2 o1 = make_float2(fmaxf(hi0, 0.0f), fmaxf(hi1, 0.0f));
        *(float2*)(out + (size_t)r0 * DD + d0)       = o0;
        *(float2*)(out + (size_t)(r0 + 1) * DD + d0) = o1;
    }
}

// ---------------------------------------------------------------------------
extern "C" void kernel_launch(void* const* d_in, const int* in_sizes, int n_in,
                              void* d_out, int out_size)
{
    const int*   entity_ids = (const int*)  d_in[0];
    const int*   adj_entity = (const int*)  d_in[1];
    const int*   adj_rel    = (const int*)  d_in[2];
    const float* ent_emb    = (const float*)d_in[3];
    const float* rel_emb    = (const float*)d_in[4];
    const float* W_att      = (const float*)d_in[5];
    const float* b_att      = (const float*)d_in[6];
    const float* W_conv     = (const float*)d_in[7];
    const float* b_conv     = (const float*)d_in[8];
    float* out = (float*)d_out;

    k_pre<<<(BN + 100 + 7) / 8, 256>>>(entity_ids, ent_emb, rel_emb, W_att);

    k_logits<<<TOT / 4 / 8, 256>>>(entity_ids, adj_entity, adj_rel,
                                   ent_emb, W_att, b_att);

    k_gather<<<BN, 64>>>(entity_ids, adj_entity, ent_emb);

    k_gemm<<<BN / GROWS, 128>>>(W_conv, b_conv, out);
}